// round 6
// baseline (speedup 1.0000x reference)
#include <cuda_runtime.h>
#include <math.h>

#define Bz   2
#define Cd   256
#define Hh   40
#define Wd   40
#define HW   1600
#define TOK  3200
#define NHd  8
#define HDd  32
#define WSd  15
#define W2Sd 225
#define MDd  7
#define HIDd 1024
#define GNg  32
#define EPSf 1e-5f
#define NEGINF -1e38f

// attention tiling
#define QT   4
#define EXT  18
#define EXT2 (EXT*EXT)     // 324
#define RP   36            // padded row stride (floats) for [pos][ch] tiles
#define SP2  232           // score row stride

// GEMM tiling
#define BN 64
#define BK 32
#define KP 36

// ---------------- scratch ----------------
__device__ float g_qln[TOK*Cd];
__device__ float g_kln[TOK*Cd];
__device__ float g_vln[TOK*Cd];
__device__ float g_Q[TOK*Cd];
__device__ float g_K[TOK*Cd];
__device__ float g_V[TOK*Cd];
__device__ float g_att[TOK*Cd];
__device__ float g_x1[TOK*Cd];
__device__ float g_ln2[TOK*Cd];
__device__ float g_h1[TOK*HIDd];
__device__ float g_cv[TOK*HIDd];
__device__ float g_gnm[Bz*GNg*2];

// ---------------- coalesced LN of img / img_warp / img_warp+mask ----------
// grid 100, block 256. block = 32 consecutive tokens x 256 channels.
__global__ void ln3_kernel(const float* __restrict__ img,
                           const float* __restrict__ imw,
                           const float* __restrict__ msk,
                           const float* __restrict__ g1,
                           const float* __restrict__ b1) {
    __shared__ float sA[256][33];
    __shared__ float sG[256], sBt[256];

    int t = threadIdx.x;
    int warp = t >> 5, lane = t & 31;
    int tok0 = blockIdx.x * 32;
    int b = tok0 / HW, p0 = tok0 % HW;

    sG[t] = g1[t]; sBt[t] = b1[t];

    const float* srcs[2] = {img, imw};
    float* outs[3] = {g_qln, g_kln, g_vln};

    for (int r = 0; r < 3; r++) {
        // load / update tile
        if (r < 2) {
            const float* src = srcs[r];
            for (int cc = warp; cc < 256; cc += 8)
                sA[cc][lane] = src[(size_t)(b*Cd + cc)*HW + p0 + lane];
        } else {
            for (int cc = warp; cc < 256; cc += 8)
                sA[cc][lane] += msk[(size_t)(b*Cd + cc)*HW + p0 + lane];
        }
        __syncthreads();

        // each warp handles 4 positions
        #pragma unroll
        for (int k = 0; k < 4; k++) {
            int p = warp*4 + k;
            float sm = 0.f, sq = 0.f;
            #pragma unroll
            for (int j = 0; j < 8; j++) {
                float v = sA[lane + 32*j][p];
                sm += v; sq += v*v;
            }
            #pragma unroll
            for (int d = 16; d > 0; d >>= 1) {
                sm += __shfl_xor_sync(0xffffffffu, sm, d);
                sq += __shfl_xor_sync(0xffffffffu, sq, d);
            }
            float mu = sm * (1.0f/Cd);
            float rs = rsqrtf(sq * (1.0f/Cd) - mu*mu + EPSf);
            float* op = outs[r] + (size_t)(tok0 + p)*Cd;
            #pragma unroll
            for (int j = 0; j < 8; j++) {
                int c = lane + 32*j;
                op[c] = (sA[c][p] - mu) * rs * sG[c] + sBt[c];
            }
        }
        __syncthreads();
    }
}

// ---------------- LN on token-major buffer ----------------
__global__ void ln_tok_kernel(const float* __restrict__ g1,
                              const float* __restrict__ b1) {
    int tok = blockIdx.x;
    int c   = threadIdx.x;
    float v = g_x1[tok*Cd + c];

    float sm = v, sq = v*v;
    #pragma unroll
    for (int d = 16; d > 0; d >>= 1) {
        sm += __shfl_xor_sync(0xffffffffu, sm, d);
        sq += __shfl_xor_sync(0xffffffffu, sq, d);
    }
    __shared__ float s1[8], s2[8], sst[2];
    int warp = c >> 5, lane = c & 31;
    if (lane == 0) { s1[warp] = sm; s2[warp] = sq; }
    __syncthreads();
    if (c == 0) {
        float ss = 0.f, qq = 0.f;
        #pragma unroll
        for (int i = 0; i < 8; i++) { ss += s1[i]; qq += s2[i]; }
        float mu = ss * (1.0f/Cd);
        sst[0] = mu;
        sst[1] = rsqrtf(qq * (1.0f/Cd) - mu*mu + EPSf);
    }
    __syncthreads();
    g_ln2[tok*Cd + c] = (v - sst[0]) * sst[1] * g1[c] + b1[c];
}

// ---------------- tf32 tensor-core GEMM, cp.async double buffered ----------
__device__ __forceinline__ unsigned f2tf32(float x) {
    unsigned r;
    asm("cvt.rna.tf32.f32 %0, %1;" : "=r"(r) : "f"(x));
    return r;
}
__device__ __forceinline__ void cp_async16(unsigned dst, const void* src) {
    asm volatile("cp.async.cg.shared.global [%0], [%1], 16;\n"
                 :: "r"(dst), "l"(src));
}
__device__ __forceinline__ void cp_commit() {
    asm volatile("cp.async.commit_group;\n");
}

// mode 0: C[m*N+n] = v
// mode 1: C[m*N+n] = v + res[(b*Cd+n)*HW+pos]
// mode 2: out[(b*Cd+n)*HW+pos] = v + res[m*N+n]
template<int BMT>
__device__ __forceinline__ void mma_body(const float* __restrict__ A, int lda,
                                         const float* __restrict__ Wt,
                                         const float* __restrict__ bias,
                                         float* __restrict__ C,
                                         int N, int K, int m0, int n0,
                                         int mode, const float* __restrict__ res) {
    constexpr int MT = BMT / 64;
    extern __shared__ float smem[];
    float* As = smem;
    float* Ws = smem + 2*BMT*KP;

    int tid  = threadIdx.x;
    int lane = tid & 31, warp = tid >> 5;
    int wm = (warp >> 1) * (16*MT), wn = (warp & 1) * 32;
    int g = lane >> 2, t4 = lane & 3;

    float acc[MT][4][4] = {};
    int steps = K / BK;

    unsigned sA = (unsigned)__cvta_generic_to_shared(As);
    unsigned sW = (unsigned)__cvta_generic_to_shared(Ws);

    auto load_stage = [&](int kc, int s) {
        int k0 = kc * BK;
        #pragma unroll
        for (int it = 0; it < BMT/32; it++) {
            int idx = tid + it*256;
            int row = idx >> 3, ch = (idx & 7) * 4;
            cp_async16(sA + (unsigned)(((s*BMT + row)*KP + ch) * 4),
                       &A[(size_t)(m0+row)*lda + k0 + ch]);
        }
        #pragma unroll
        for (int it = 0; it < 2; it++) {
            int idx = tid + it*256;
            int row = idx >> 3, ch = (idx & 7) * 4;
            cp_async16(sW + (unsigned)(((s*BN + row)*KP + ch) * 4),
                       &Wt[(size_t)(n0+row)*K + k0 + ch]);
        }
        cp_commit();
    };

    load_stage(0, 0);

    for (int kc = 0; kc < steps; kc++) {
        int s = kc & 1;
        if (kc + 1 < steps) {
            load_stage(kc + 1, (kc + 1) & 1);
            asm volatile("cp.async.wait_group 1;\n");
        } else {
            asm volatile("cp.async.wait_group 0;\n");
        }
        __syncthreads();

        float* Ab = As + s*BMT*KP;
        float* Wb = Ws + s*BN*KP;
        #pragma unroll
        for (int ks = 0; ks < BK; ks += 8) {
            unsigned a[MT][4], bf[4][2];
            #pragma unroll
            for (int mt = 0; mt < MT; mt++) {
                int rb = wm + mt*16;
                a[mt][0] = f2tf32(Ab[(rb + g    )*KP + ks + t4    ]);
                a[mt][1] = f2tf32(Ab[(rb + g + 8)*KP + ks + t4    ]);
                a[mt][2] = f2tf32(Ab[(rb + g    )*KP + ks + t4 + 4]);
                a[mt][3] = f2tf32(Ab[(rb + g + 8)*KP + ks + t4 + 4]);
            }
            #pragma unroll
            for (int nt = 0; nt < 4; nt++) {
                int nb = wn + nt*8 + g;
                bf[nt][0] = f2tf32(Wb[nb*KP + ks + t4    ]);
                bf[nt][1] = f2tf32(Wb[nb*KP + ks + t4 + 4]);
            }
            #pragma unroll
            for (int mt = 0; mt < MT; mt++)
                #pragma unroll
                for (int nt = 0; nt < 4; nt++)
                    asm volatile(
                        "mma.sync.aligned.m16n8k8.row.col.f32.tf32.tf32.f32 "
                        "{%0,%1,%2,%3}, {%4,%5,%6,%7}, {%8,%9}, {%0,%1,%2,%3};"
                        : "+f"(acc[mt][nt][0]), "+f"(acc[mt][nt][1]),
                          "+f"(acc[mt][nt][2]), "+f"(acc[mt][nt][3])
                        : "r"(a[mt][0]), "r"(a[mt][1]),
                          "r"(a[mt][2]), "r"(a[mt][3]),
                          "r"(bf[nt][0]), "r"(bf[nt][1]));
        }
        __syncthreads();
    }

    #pragma unroll
    for (int mt = 0; mt < MT; mt++) {
        #pragma unroll
        for (int nt = 0; nt < 4; nt++) {
            #pragma unroll
            for (int i = 0; i < 4; i++) {
                int mrow = m0 + wm + mt*16 + g + ((i >= 2) ? 8 : 0);
                int ncol = n0 + wn + nt*8 + 2*t4 + (i & 1);
                float v = acc[mt][nt][i] + bias[ncol];
                if (mode == 0) {
                    C[(size_t)mrow*N + ncol] = v;
                } else if (mode == 1) {
                    int b = mrow / HW, pos = mrow % HW;
                    C[(size_t)mrow*N + ncol] =
                        v + res[(size_t)(b*Cd + ncol)*HW + pos];
                } else {
                    int b = mrow / HW, pos = mrow % HW;
                    C[(size_t)(b*Cd + ncol)*HW + pos] =
                        v + res[(size_t)mrow*N + ncol];
                }
            }
        }
    }
}

template<int BMT>
__global__ void mma_gemm_kernel(const float* __restrict__ A,
                                const float* __restrict__ Wt,
                                const float* __restrict__ bias,
                                float* __restrict__ C,
                                int N, int K, int mode,
                                const float* __restrict__ res) {
    mma_body<BMT>(A, K, Wt, bias, C, N, K, blockIdx.y*BMT, blockIdx.x*BN, mode, res);
}

struct QKVArgs {
    const float* A[3];
    const float* W[3];
    const float* bias[3];
    float* C[3];
};
__global__ void mma_qkv_kernel(QKVArgs args) {
    int z = blockIdx.z;
    mma_body<128>(args.A[z], Cd, args.W[z], args.bias[z], args.C[z],
                  Cd, Cd, blockIdx.y*128, blockIdx.x*BN, 0, nullptr);
}

// ---------------- tiled local attention, float4 smem layout ----------------
__global__ void attn_tile_kernel(const float* __restrict__ Wrel,
                                 const float* __restrict__ brel) {
    extern __shared__ float smem[];
    float* sK   = smem;                  // [328][RP]   K window (then V), [pos][ch]
    float* sW   = sK + 328*RP;           // [228][RP]   Wrel[h], [o][ch]
    float* sS   = sW + 228*RP;           // [16][SP2]
    float* sInv = sS + 16*SP2;           // [16]
    float* sbr  = sInv + 16;             // [228]

    int tile = blockIdx.x;
    int h = blockIdx.y, b = blockIdx.z;
    int ty0 = (tile / (Wd/QT)) * QT;
    int tx0 = (tile % (Wd/QT)) * QT;
    int t = threadIdx.x;

    // load Wrel[h] as [o][ch]
    for (int i = t; i < W2Sd*32; i += 256) {
        int o = i >> 5, c = i & 31;
        sW[o*RP + c] = Wrel[(h*W2Sd + o)*HDd + c];
    }
    if (t < W2Sd) sbr[t] = brel[h*W2Sd + t];

    // load K window as [pos][ch], zero-padded OOB
    int wy0 = ty0 - MDd, wx0 = tx0 - MDd;
    for (int i = t; i < EXT2*32; i += 256) {
        int pos = i >> 5, c = i & 31;
        int wy = pos / EXT, wx = pos - (pos/EXT)*EXT;
        int ky = wy0 + wy, kx = wx0 + wx;
        float v = 0.f;
        if (ky >= 0 && ky < Hh && kx >= 0 && kx < Wd)
            v = g_K[(size_t)(b*HW + ky*Wd + kx)*Cd + h*HDd + c];
        sK[pos*RP + c] = v;
    }

    int q  = t >> 4, lo = t & 15;
    int qy = q >> 2, qx = q & 3;
    int ty = ty0 + qy, tx = tx0 + qx;
    int tok = b*HW + ty*Wd + tx;
    float4 qv[8];
    {
        const float4* qp = (const float4*)(g_Q + (size_t)tok*Cd + h*HDd);
        #pragma unroll
        for (int j = 0; j < 8; j++) qv[j] = qp[j];
    }
    __syncthreads();

    const float scale = 0.17677669529663687f;
    for (int o = lo; o < W2Sd; o += 16) {
        int oy = o / WSd, ox = o - oy*WSd;
        int ky = ty + oy - MDd, kx = tx + ox - MDd;
        float s = NEGINF;
        if (ky >= 0 && ky < Hh && kx >= 0 && kx < Wd) {
            int pos = (qy + oy)*EXT + (qx + ox);
            const float4* kp = (const float4*)(sK + pos*RP);
            const float4* wp = (const float4*)(sW + o*RP);
            float d = 0.f, r = 0.f;
            #pragma unroll
            for (int j = 0; j < 8; j++) {
                float4 kk = kp[j], ww = wp[j], qq = qv[j];
                d += qq.x*kk.x + qq.y*kk.y + qq.z*kk.z + qq.w*kk.w;
                r += qq.x*ww.x + qq.y*ww.y + qq.z*ww.z + qq.w*ww.w;
            }
            s = d*scale + r + sbr[o];
        }
        sS[q*SP2 + o] = s;
    }
    __syncthreads();

    // softmax: 16 lanes per query
    {
        float mx = NEGINF;
        for (int o = lo; o < W2Sd; o += 16)
            mx = fmaxf(mx, sS[q*SP2 + o]);
        #pragma unroll
        for (int d = 8; d > 0; d >>= 1)
            mx = fmaxf(mx, __shfl_xor_sync(0xffffffffu, mx, d));
        float sum = 0.f;
        for (int o = lo; o < W2Sd; o += 16) {
            float s = sS[q*SP2 + o];
            float e = (s > -1e37f) ? __expf(s - mx) : 0.f;
            sS[q*SP2 + o] = e;
            sum += e;
        }
        #pragma unroll
        for (int d = 8; d > 0; d >>= 1)
            sum += __shfl_xor_sync(0xffffffffu, sum, d);
        if (lo == 0) sInv[q] = 1.f / sum;
    }
    __syncthreads();

    // load V window (reuse sK, same [pos][ch] layout)
    for (int i = t; i < EXT2*32; i += 256) {
        int pos = i >> 5, c = i & 31;
        int wy = pos / EXT, wx = pos - (pos/EXT)*EXT;
        int ky = wy0 + wy, kx = wx0 + wx;
        float v = 0.f;
        if (ky >= 0 && ky < Hh && kx >= 0 && kx < Wd)
            v = g_V[(size_t)(b*HW + ky*Wd + kx)*Cd + h*HDd + c];
        sK[pos*RP + c] = v;
    }
    __syncthreads();

    // weighted V sum (invalid offsets have p=0, V zero-padded -> no mask needed)
    int c = t & 31, q8 = t >> 5;
    #pragma unroll
    for (int rep = 0; rep < 2; rep++) {
        int qq = q8 + rep*8;
        int qqy = qq >> 2, qqx = qq & 3;
        float acc = 0.f;
        #pragma unroll
        for (int oy = 0; oy < WSd; oy++) {
            int pos0 = (qqy + oy)*EXT + qqx;
            int srow = qq*SP2 + oy*WSd;
            #pragma unroll
            for (int ox = 0; ox < WSd; ox++)
                acc += sS[srow + ox] * sK[(pos0 + ox)*RP + c];
        }
        int tok2 = b*HW + (ty0 + qqy)*Wd + (tx0 + qqx);
        g_att[(size_t)tok2*Cd + h*HDd + c] = acc * sInv[qq];
    }
}

// ---------------- GroupNorm stats per (b, group) ----------------
__global__ void gn_stats_kernel() {
    int bg = blockIdx.x;
    int b = bg / GNg, g = bg % GNg;
    int tid = threadIdx.x;
    float sm = 0.f, sq = 0.f;
    for (int i = tid; i < HW*32; i += 256) {
        int ch  = g*32 + (i & 31);
        int pos = i >> 5;
        float v = g_h1[(size_t)(b*HW + pos)*HIDd + ch];
        sm += v; sq += v*v;
    }
    #pragma unroll
    for (int d = 16; d > 0; d >>= 1) {
        sm += __shfl_xor_sync(0xffffffffu, sm, d);
        sq += __shfl_xor_sync(0xffffffffu, sq, d);
    }
    __shared__ float s1[8], s2[8];
    int warp = tid >> 5, lane = tid & 31;
    if (lane == 0) { s1[warp] = sm; s2[warp] = sq; }
    __syncthreads();
    if (tid == 0) {
        float ss = 0.f, qq = 0.f;
        #pragma unroll
        for (int i = 0; i < 8; i++) { ss += s1[i]; qq += s2[i]; }
        float cnt = (float)(HW*32);
        float mu  = ss / cnt;
        float var = qq / cnt - mu*mu;
        g_gnm[bg*2]   = mu;
        g_gnm[bg*2+1] = rsqrtf(var + EPSf);
    }
}

// ---------------- fused GN + GELU + 5x5 depthwise conv ----------------
__global__ void dwconv_fused_kernel(const float* __restrict__ gg,
                                    const float* __restrict__ gb,
                                    const float* __restrict__ Wdw) {
    __shared__ float sT[144][68];

    int tileid = blockIdx.x;
    int cg = blockIdx.y, b = blockIdx.z;
    int ty0 = (tileid / 5) * 8, tx0 = (tileid % 5) * 8;
    int tid = threadIdx.x;
    int ch  = tid & 63;
    int chg = cg*64 + ch;

    float gamma = gg[chg], beta = gb[chg];
    int grp = chg >> 5;
    float mu = g_gnm[(b*GNg + grp)*2];
    float rs = g_gnm[(b*GNg + grp)*2 + 1];

    float wreg[25];
    #pragma unroll
    for (int i = 0; i < 25; i++) wreg[i] = Wdw[chg*25 + i];

    for (int i = tid; i < 144*64; i += 256) {
        int pos = i >> 6;
        int wy = pos / 12, wx = pos - (pos/12)*12;
        int y = ty0 + wy - 2, x = tx0 + wx - 2;
        float v = 0.f;
        if (y >= 0 && y < Hh && x >= 0 && x < Wd) {
            float hv = g_h1[(size_t)(b*HW + y*Wd + x)*HIDd + chg];
            hv = (hv - mu) * rs * gamma + beta;
            v = 0.5f * hv * (1.f + erff(hv * 0.70710678118654752f));
        }
        sT[pos][ch] = v;
    }
    __syncthreads();

    int pg = tid >> 6;
    #pragma unroll
    for (int p = 0; p < 16; p++) {
        int po = pg*16 + p;
        int y = po >> 3, x = po & 7;
        float acc = 0.f;
        #pragma unroll
        for (int dy = 0; dy < 5; dy++)
            #pragma unroll
            for (int dx = 0; dx < 5; dx++)
                acc += wreg[dy*5+dx] * sT[(y+dy)*12 + (x+dx)][ch];
        g_cv[(size_t)(b*HW + (ty0+y)*Wd + (tx0+x))*HIDd + chg] = acc;
    }
}

// ---------------- launch ----------------
extern "C" void kernel_launch(void* const* d_in, const int* in_sizes, int n_in,
                              void* d_out, int out_size) {
    const float* img   = (const float*)d_in[0];
    const float* imw   = (const float*)d_in[1];
    const float* msk   = (const float*)d_in[2];
    const float* ln1g  = (const float*)d_in[3];
    const float* ln1b  = (const float*)d_in[4];
    const float* ln2g  = (const float*)d_in[5];
    const float* ln2b  = (const float*)d_in[6];
    const float* Wq    = (const float*)d_in[7];
    const float* bq    = (const float*)d_in[8];
    const float* Wk    = (const float*)d_in[9];
    const float* bk    = (const float*)d_in[10];
    const float* Wv    = (const float*)d_in[11];
    const float* bv    = (const float*)d_in[12];
    const float* Wrel  = (const float*)d_in[13];
    const float* brel  = (const float*)d_in[14];
    const float* Wproj = (const float*)d_in[15];
    const float* bproj = (const float*)d_in[16];
    const float* W1    = (const float*)d_in[17];
    const float* bW1   = (const float*)d_in[18];
    const float* gng   = (const float*)d_in[19];
    const float* gnb   = (const float*)d_in[20];
    const float* Wdw   = (const float*)d_in[21];
    const float* W2    = (const float*)d_in[22];
    const float* bW2   = (const float*)d_in[23];
    float* out = (float*)d_out;

    float *qln, *kln, *vln, *Q, *K, *V, *att, *x1, *ln2, *h1, *cv;
    cudaGetSymbolAddress((void**)&qln, g_qln);
    cudaGetSymbolAddress((void**)&kln, g_kln);
    cudaGetSymbolAddress((void**)&vln, g_vln);
    cudaGetSymbolAddress((void**)&Q,   g_Q);
    cudaGetSymbolAddress((void**)&K,   g_K);
    cudaGetSymbolAddress((void**)&V,   g_V);
    cudaGetSymbolAddress((void**)&att, g_att);
    cudaGetSymbolAddress((void**)&x1,  g_x1);
    cudaGetSymbolAddress((void**)&ln2, g_ln2);
    cudaGetSymbolAddress((void**)&h1,  g_h1);
    cudaGetSymbolAddress((void**)&cv,  g_cv);

    int smem128 = (2*128*KP + 2*BN*KP) * sizeof(float);
    int smem64  = (2*64*KP  + 2*BN*KP) * sizeof(float);
    cudaFuncSetAttribute(mma_gemm_kernel<128>,
                         cudaFuncAttributeMaxDynamicSharedMemorySize, smem128);
    cudaFuncSetAttribute(mma_gemm_kernel<64>,
                         cudaFuncAttributeMaxDynamicSharedMemorySize, smem64);
    cudaFuncSetAttribute(mma_qkv_kernel,
                         cudaFuncAttributeMaxDynamicSharedMemorySize, smem128);

    // 1. LayerNorms (coalesced)
    ln3_kernel<<<TOK/32, 256>>>(img, imw, msk, ln1g, ln1b);

    // 2. QKV projections
    QKVArgs qa;
    qa.A[0] = qln; qa.A[1] = kln; qa.A[2] = vln;
    qa.W[0] = Wq;  qa.W[1] = Wk;  qa.W[2] = Wv;
    qa.bias[0] = bq; qa.bias[1] = bk; qa.bias[2] = bv;
    qa.C[0] = Q; qa.C[1] = K; qa.C[2] = V;
    mma_qkv_kernel<<<dim3(Cd/BN, TOK/128, 3), 256, smem128>>>(qa);

    // 3. tiled windowed attention (inline rel, float4 layouts)
    int attn_smem = (328*RP + 228*RP + 16*SP2 + 16 + 228) * sizeof(float);
    cudaFuncSetAttribute(attn_tile_kernel,
                         cudaFuncAttributeMaxDynamicSharedMemorySize, attn_smem);
    attn_tile_kernel<<<dim3((Hh/QT)*(Wd/QT), NHd, Bz), 256, attn_smem>>>(Wrel, brel);

    // 4. output projection + fused residual -> x1
    mma_gemm_kernel<64><<<dim3(Cd/BN, TOK/64), 256, smem64>>>(att, Wproj, bproj, x1,
                                                              Cd, Cd, 1, img);

    // 5. MLP branch
    ln_tok_kernel<<<TOK, 256>>>(ln2g, ln2b);
    mma_gemm_kernel<128><<<dim3(HIDd/BN, TOK/128), 256, smem128>>>(ln2, W1, bW1, h1,
                                                                   HIDd, Cd, 0, nullptr);
    gn_stats_kernel<<<Bz*GNg, 256>>>();
    dwconv_fused_kernel<<<dim3(25, HIDd/64, Bz), 256>>>(gng, gnb, Wdw);

    // 6. W2 + fused final residual + transpose to BCHW
    mma_gemm_kernel<64><<<dim3(Cd/BN, TOK/64), 256, smem64>>>(cv, W2, bW2, out,
                                                              Cd, HIDd, 2, x1);
}

// round 7
// speedup vs baseline: 1.0322x; 1.0322x over previous
#include <cuda_runtime.h>
#include <math.h>

#define Bz   2
#define Cd   256
#define Hh   40
#define Wd   40
#define HW   1600
#define TOK  3200
#define NHd  8
#define HDd  32
#define WSd  15
#define W2Sd 225
#define MDd  7
#define HIDd 1024
#define GNg  32
#define EPSf 1e-5f
#define NEGINF -1e38f

// attention tiling (round-4 proven layout)
#define QT   4
#define EXT  18
#define EXT2 (EXT*EXT)
#define KPAD 325
#define WPAD 225
#define SPAD 228

// GEMM tiling
#define BN 64
#define BK 32
#define KP 36

// ---------------- scratch ----------------
__device__ float g_qln[TOK*Cd];
__device__ float g_kln[TOK*Cd];
__device__ float g_vln[TOK*Cd];
__device__ float g_Q[TOK*Cd];
__device__ float g_K[TOK*Cd];
__device__ float g_V[TOK*Cd];
__device__ float g_att[TOK*Cd];
__device__ float g_x1[TOK*Cd];
__device__ float g_ln2[TOK*Cd];
__device__ float g_h1[TOK*HIDd];
__device__ float g_cv[TOK*HIDd];
__device__ float g_gnm[Bz*GNg*2];

// ---------------- coalesced LN of img / img_warp / img_warp+mask ----------
__global__ void ln3_kernel(const float* __restrict__ img,
                           const float* __restrict__ imw,
                           const float* __restrict__ msk,
                           const float* __restrict__ g1,
                           const float* __restrict__ b1) {
    __shared__ float sA[256][33];
    __shared__ float sG[256], sBt[256];

    int t = threadIdx.x;
    int warp = t >> 5, lane = t & 31;
    int tok0 = blockIdx.x * 32;
    int b = tok0 / HW, p0 = tok0 % HW;

    sG[t] = g1[t]; sBt[t] = b1[t];

    const float* srcs[2] = {img, imw};
    float* outs[3] = {g_qln, g_kln, g_vln};

    for (int r = 0; r < 3; r++) {
        if (r < 2) {
            const float* src = srcs[r];
            for (int cc = warp; cc < 256; cc += 8)
                sA[cc][lane] = src[(size_t)(b*Cd + cc)*HW + p0 + lane];
        } else {
            for (int cc = warp; cc < 256; cc += 8)
                sA[cc][lane] += msk[(size_t)(b*Cd + cc)*HW + p0 + lane];
        }
        __syncthreads();

        #pragma unroll
        for (int k = 0; k < 4; k++) {
            int p = warp*4 + k;
            float sm = 0.f, sq = 0.f;
            #pragma unroll
            for (int j = 0; j < 8; j++) {
                float v = sA[lane + 32*j][p];
                sm += v; sq += v*v;
            }
            #pragma unroll
            for (int d = 16; d > 0; d >>= 1) {
                sm += __shfl_xor_sync(0xffffffffu, sm, d);
                sq += __shfl_xor_sync(0xffffffffu, sq, d);
            }
            float mu = sm * (1.0f/Cd);
            float rs = rsqrtf(sq * (1.0f/Cd) - mu*mu + EPSf);
            float* op = outs[r] + (size_t)(tok0 + p)*Cd;
            #pragma unroll
            for (int j = 0; j < 8; j++) {
                int c = lane + 32*j;
                op[c] = (sA[c][p] - mu) * rs * sG[c] + sBt[c];
            }
        }
        __syncthreads();
    }
}

// ---------------- LN on token-major buffer ----------------
__global__ void ln_tok_kernel(const float* __restrict__ g1,
                              const float* __restrict__ b1) {
    int tok = blockIdx.x;
    int c   = threadIdx.x;
    float v = g_x1[tok*Cd + c];

    float sm = v, sq = v*v;
    #pragma unroll
    for (int d = 16; d > 0; d >>= 1) {
        sm += __shfl_xor_sync(0xffffffffu, sm, d);
        sq += __shfl_xor_sync(0xffffffffu, sq, d);
    }
    __shared__ float s1[8], s2[8], sst[2];
    int warp = c >> 5, lane = c & 31;
    if (lane == 0) { s1[warp] = sm; s2[warp] = sq; }
    __syncthreads();
    if (c == 0) {
        float ss = 0.f, qq = 0.f;
        #pragma unroll
        for (int i = 0; i < 8; i++) { ss += s1[i]; qq += s2[i]; }
        float mu = ss * (1.0f/Cd);
        sst[0] = mu;
        sst[1] = rsqrtf(qq * (1.0f/Cd) - mu*mu + EPSf);
    }
    __syncthreads();
    g_ln2[tok*Cd + c] = (v - sst[0]) * sst[1] * g1[c] + b1[c];
}

// ---------------- tf32 tensor-core GEMM, cp.async double buffered ----------
__device__ __forceinline__ unsigned f2tf32(float x) {
    unsigned r;
    asm("cvt.rna.tf32.f32 %0, %1;" : "=r"(r) : "f"(x));
    return r;
}
__device__ __forceinline__ void cp_async16(unsigned dst, const void* src) {
    asm volatile("cp.async.cg.shared.global [%0], [%1], 16;\n"
                 :: "r"(dst), "l"(src));
}
__device__ __forceinline__ void cp_commit() {
    asm volatile("cp.async.commit_group;\n");
}

// mode 0: C[m*N+n] = v
// mode 1: C[m*N+n] = v + res[(b*Cd+n)*HW+pos]
// mode 2: out[(b*Cd+n)*HW+pos] = v + res[m*N+n]
template<int BMT>
__device__ __forceinline__ void mma_body(const float* __restrict__ A, int lda,
                                         const float* __restrict__ Wt,
                                         const float* __restrict__ bias,
                                         float* __restrict__ C,
                                         int N, int K, int m0, int n0,
                                         int mode, const float* __restrict__ res) {
    constexpr int MT = BMT / 64;
    extern __shared__ float smem[];
    float* As = smem;
    float* Ws = smem + 2*BMT*KP;

    int tid  = threadIdx.x;
    int lane = tid & 31, warp = tid >> 5;
    int wm = (warp >> 1) * (16*MT), wn = (warp & 1) * 32;
    int g = lane >> 2, t4 = lane & 3;

    float acc[MT][4][4] = {};
    int steps = K / BK;

    unsigned sA = (unsigned)__cvta_generic_to_shared(As);
    unsigned sW = (unsigned)__cvta_generic_to_shared(Ws);

    auto load_stage = [&](int kc, int s) {
        int k0 = kc * BK;
        #pragma unroll
        for (int it = 0; it < BMT/32; it++) {
            int idx = tid + it*256;
            int row = idx >> 3, ch = (idx & 7) * 4;
            cp_async16(sA + (unsigned)(((s*BMT + row)*KP + ch) * 4),
                       &A[(size_t)(m0+row)*lda + k0 + ch]);
        }
        #pragma unroll
        for (int it = 0; it < 2; it++) {
            int idx = tid + it*256;
            int row = idx >> 3, ch = (idx & 7) * 4;
            cp_async16(sW + (unsigned)(((s*BN + row)*KP + ch) * 4),
                       &Wt[(size_t)(n0+row)*K + k0 + ch]);
        }
        cp_commit();
    };

    load_stage(0, 0);

    for (int kc = 0; kc < steps; kc++) {
        int s = kc & 1;
        if (kc + 1 < steps) {
            load_stage(kc + 1, (kc + 1) & 1);
            asm volatile("cp.async.wait_group 1;\n");
        } else {
            asm volatile("cp.async.wait_group 0;\n");
        }
        __syncthreads();

        float* Ab = As + s*BMT*KP;
        float* Wb = Ws + s*BN*KP;
        #pragma unroll
        for (int ks = 0; ks < BK; ks += 8) {
            unsigned a[MT][4], bf[4][2];
            #pragma unroll
            for (int mt = 0; mt < MT; mt++) {
                int rb = wm + mt*16;
                a[mt][0] = f2tf32(Ab[(rb + g    )*KP + ks + t4    ]);
                a[mt][1] = f2tf32(Ab[(rb + g + 8)*KP + ks + t4    ]);
                a[mt][2] = f2tf32(Ab[(rb + g    )*KP + ks + t4 + 4]);
                a[mt][3] = f2tf32(Ab[(rb + g + 8)*KP + ks + t4 + 4]);
            }
            #pragma unroll
            for (int nt = 0; nt < 4; nt++) {
                int nb = wn + nt*8 + g;
                bf[nt][0] = f2tf32(Wb[nb*KP + ks + t4    ]);
                bf[nt][1] = f2tf32(Wb[nb*KP + ks + t4 + 4]);
            }
            #pragma unroll
            for (int mt = 0; mt < MT; mt++)
                #pragma unroll
                for (int nt = 0; nt < 4; nt++)
                    asm volatile(
                        "mma.sync.aligned.m16n8k8.row.col.f32.tf32.tf32.f32 "
                        "{%0,%1,%2,%3}, {%4,%5,%6,%7}, {%8,%9}, {%0,%1,%2,%3};"
                        : "+f"(acc[mt][nt][0]), "+f"(acc[mt][nt][1]),
                          "+f"(acc[mt][nt][2]), "+f"(acc[mt][nt][3])
                        : "r"(a[mt][0]), "r"(a[mt][1]),
                          "r"(a[mt][2]), "r"(a[mt][3]),
                          "r"(bf[nt][0]), "r"(bf[nt][1]));
        }
        __syncthreads();
    }

    #pragma unroll
    for (int mt = 0; mt < MT; mt++) {
        #pragma unroll
        for (int nt = 0; nt < 4; nt++) {
            #pragma unroll
            for (int i = 0; i < 4; i++) {
                int mrow = m0 + wm + mt*16 + g + ((i >= 2) ? 8 : 0);
                int ncol = n0 + wn + nt*8 + 2*t4 + (i & 1);
                float v = acc[mt][nt][i] + bias[ncol];
                if (mode == 0) {
                    C[(size_t)mrow*N + ncol] = v;
                } else if (mode == 1) {
                    int b = mrow / HW, pos = mrow % HW;
                    C[(size_t)mrow*N + ncol] =
                        v + res[(size_t)(b*Cd + ncol)*HW + pos];
                } else {
                    int b = mrow / HW, pos = mrow % HW;
                    C[(size_t)(b*Cd + ncol)*HW + pos] =
                        v + res[(size_t)mrow*N + ncol];
                }
            }
        }
    }
}

template<int BMT>
__global__ void mma_gemm_kernel(const float* __restrict__ A,
                                const float* __restrict__ Wt,
                                const float* __restrict__ bias,
                                float* __restrict__ C,
                                int N, int K, int mode,
                                const float* __restrict__ res) {
    mma_body<BMT>(A, K, Wt, bias, C, N, K, blockIdx.y*BMT, blockIdx.x*BN, mode, res);
}

struct QKVArgs {
    const float* A[3];
    const float* W[3];
    const float* bias[3];
    float* C[3];
};
__global__ void mma_qkv_kernel(QKVArgs args) {
    int z = blockIdx.z;
    mma_body<128>(args.A[z], Cd, args.W[z], args.bias[z], args.C[z],
                  Cd, Cd, blockIdx.y*128, blockIdx.x*BN, 0, nullptr);
}

// ---------------- tiled local attention (round-4 proven version) ----------
__global__ void attn_tile_kernel(const float* __restrict__ Wrel,
                                 const float* __restrict__ brel) {
    extern __shared__ float smem[];
    float* sK   = smem;                 // [32][KPAD]
    float* sW   = sK + 32*KPAD;         // [32][WPAD]
    float* sS   = sW + 32*WPAD;         // [16][SPAD]
    float* sInv = sS + 16*SPAD;         // [16]

    int tile = blockIdx.x;
    int h = blockIdx.y, b = blockIdx.z;
    int ty0 = (tile / (Wd/QT)) * QT;
    int tx0 = (tile % (Wd/QT)) * QT;
    int t = threadIdx.x;

    for (int i = t; i < W2Sd*32; i += 256) {
        int o = i >> 5, c = i & 31;
        sW[c*WPAD + o] = Wrel[(h*W2Sd + o)*HDd + c];
    }
    int wy0 = ty0 - MDd, wx0 = tx0 - MDd;
    for (int i = t; i < EXT2*32; i += 256) {
        int pos = i >> 5, c = i & 31;
        int wy = pos / EXT, wx = pos - (pos/EXT)*EXT;
        int ky = wy0 + wy, kx = wx0 + wx;
        float v = 0.f;
        if (ky >= 0 && ky < Hh && kx >= 0 && kx < Wd)
            v = g_K[(size_t)(b*HW + ky*Wd + kx)*Cd + h*HDd + c];
        sK[c*KPAD + pos] = v;
    }

    int q  = t >> 4;
    int lo = t & 15;
    int qy = q >> 2, qx = q & 3;
    int ty = ty0 + qy, tx = tx0 + qx;
    int tok = b*HW + ty*Wd + tx;
    float qreg[32];
    {
        const float* qp = g_Q + (size_t)tok*Cd + h*HDd;
        #pragma unroll
        for (int c = 0; c < 32; c++) qreg[c] = qp[c];
    }
    __syncthreads();

    const float scale = 0.17677669529663687f;
    for (int o = lo; o < W2Sd; o += 16) {
        int oy = o / WSd, ox = o - (o/WSd)*WSd;
        int ky = ty + oy - MDd, kx = tx + ox - MDd;
        float s = NEGINF;
        if (ky >= 0 && ky < Hh && kx >= 0 && kx < Wd) {
            int pos = (qy + oy)*EXT + (qx + ox);
            float d = 0.f, r = 0.f;
            #pragma unroll
            for (int c = 0; c < 32; c++) {
                d += qreg[c] * sK[c*KPAD + pos];
                r += qreg[c] * sW[c*WPAD + o];
            }
            s = d*scale + r + brel[h*W2Sd + o];
        }
        sS[q*SPAD + o] = s;
    }
    __syncthreads();

    {
        float mx = NEGINF;
        for (int o = lo; o < W2Sd; o += 16)
            mx = fmaxf(mx, sS[q*SPAD + o]);
        #pragma unroll
        for (int d = 8; d > 0; d >>= 1)
            mx = fmaxf(mx, __shfl_xor_sync(0xffffffffu, mx, d));
        float sum = 0.f;
        for (int o = lo; o < W2Sd; o += 16) {
            float s = sS[q*SPAD + o];
            float e = (s > -1e37f) ? __expf(s - mx) : 0.f;
            sS[q*SPAD + o] = e;
            sum += e;
        }
        #pragma unroll
        for (int d = 8; d > 0; d >>= 1)
            sum += __shfl_xor_sync(0xffffffffu, sum, d);
        if (lo == 0) sInv[q] = 1.f / sum;
    }
    __syncthreads();

    for (int i = t; i < EXT2*32; i += 256) {
        int pos = i >> 5, c = i & 31;
        int wy = pos / EXT, wx = pos - (pos/EXT)*EXT;
        int ky = wy0 + wy, kx = wx0 + wx;
        float v = 0.f;
        if (ky >= 0 && ky < Hh && kx >= 0 && kx < Wd)
            v = g_V[(size_t)(b*HW + ky*Wd + kx)*Cd + h*HDd + c];
        sK[c*KPAD + pos] = v;
    }
    __syncthreads();

    int c = t & 31, q8 = t >> 5;
    #pragma unroll
    for (int rep = 0; rep < 2; rep++) {
        int qq = q8 + rep*8;
        int qqy = qq >> 2, qqx = qq & 3;
        float acc = 0.f;
        #pragma unroll
        for (int oy = 0; oy < WSd; oy++) {
            int rowbase = (qqy + oy)*EXT + qqx;
            int srow = qq*SPAD + oy*WSd;
            #pragma unroll
            for (int ox = 0; ox < WSd; ox++)
                acc += sS[srow + ox] * sK[c*KPAD + rowbase + ox];
        }
        int tok2 = b*HW + (ty0 + qqy)*Wd + (tx0 + qqx);
        g_att[(size_t)tok2*Cd + h*HDd + c] = acc * sInv[qq];
    }
}

// ---------------- GroupNorm stats per (b, group) ----------------
__global__ void gn_stats_kernel() {
    int bg = blockIdx.x;
    int b = bg / GNg, g = bg % GNg;
    int tid = threadIdx.x;
    float sm = 0.f, sq = 0.f;
    for (int i = tid; i < HW*32; i += 256) {
        int ch  = g*32 + (i & 31);
        int pos = i >> 5;
        float v = g_h1[(size_t)(b*HW + pos)*HIDd + ch];
        sm += v; sq += v*v;
    }
    #pragma unroll
    for (int d = 16; d > 0; d >>= 1) {
        sm += __shfl_xor_sync(0xffffffffu, sm, d);
        sq += __shfl_xor_sync(0xffffffffu, sq, d);
    }
    __shared__ float s1[8], s2[8];
    int warp = tid >> 5, lane = tid & 31;
    if (lane == 0) { s1[warp] = sm; s2[warp] = sq; }
    __syncthreads();
    if (tid == 0) {
        float ss = 0.f, qq = 0.f;
        #pragma unroll
        for (int i = 0; i < 8; i++) { ss += s1[i]; qq += s2[i]; }
        float cnt = (float)(HW*32);
        float mu  = ss / cnt;
        float var = qq / cnt - mu*mu;
        g_gnm[bg*2]   = mu;
        g_gnm[bg*2+1] = rsqrtf(var + EPSf);
    }
}

// ---------------- fused GN + GELU + 5x5 depthwise conv ----------------
__global__ void dwconv_fused_kernel(const float* __restrict__ gg,
                                    const float* __restrict__ gb,
                                    const float* __restrict__ Wdw) {
    __shared__ float sT[144][68];

    int tileid = blockIdx.x;
    int cg = blockIdx.y, b = blockIdx.z;
    int ty0 = (tileid / 5) * 8, tx0 = (tileid % 5) * 8;
    int tid = threadIdx.x;
    int ch  = tid & 63;
    int chg = cg*64 + ch;

    float gamma = gg[chg], beta = gb[chg];
    int grp = chg >> 5;
    float mu = g_gnm[(b*GNg + grp)*2];
    float rs = g_gnm[(b*GNg + grp)*2 + 1];

    float wreg[25];
    #pragma unroll
    for (int i = 0; i < 25; i++) wreg[i] = Wdw[chg*25 + i];

    for (int i = tid; i < 144*64; i += 256) {
        int pos = i >> 6;
        int wy = pos / 12, wx = pos - (pos/12)*12;
        int y = ty0 + wy - 2, x = tx0 + wx - 2;
        float v = 0.f;
        if (y >= 0 && y < Hh && x >= 0 && x < Wd) {
            float hv = g_h1[(size_t)(b*HW + y*Wd + x)*HIDd + chg];
            hv = (hv - mu) * rs * gamma + beta;
            v = 0.5f * hv * (1.f + erff(hv * 0.70710678118654752f));
        }
        sT[pos][ch] = v;
    }
    __syncthreads();

    int pg = tid >> 6;
    #pragma unroll
    for (int p = 0; p < 16; p++) {
        int po = pg*16 + p;
        int y = po >> 3, x = po & 7;
        float acc = 0.f;
        #pragma unroll
        for (int dy = 0; dy < 5; dy++)
            #pragma unroll
            for (int dx = 0; dx < 5; dx++)
                acc += wreg[dy*5+dx] * sT[(y+dy)*12 + (x+dx)][ch];
        g_cv[(size_t)(b*HW + (ty0+y)*Wd + (tx0+x))*HIDd + chg] = acc;
    }
}

// ---------------- launch ----------------
extern "C" void kernel_launch(void* const* d_in, const int* in_sizes, int n_in,
                              void* d_out, int out_size) {
    const float* img   = (const float*)d_in[0];
    const float* imw   = (const float*)d_in[1];
    const float* msk   = (const float*)d_in[2];
    const float* ln1g  = (const float*)d_in[3];
    const float* ln1b  = (const float*)d_in[4];
    const float* ln2g  = (const float*)d_in[5];
    const float* ln2b  = (const float*)d_in[6];
    const float* Wq    = (const float*)d_in[7];
    const float* bq    = (const float*)d_in[8];
    const float* Wk    = (const float*)d_in[9];
    const float* bk    = (const float*)d_in[10];
    const float* Wv    = (const float*)d_in[11];
    const float* bv    = (const float*)d_in[12];
    const float* Wrel  = (const float*)d_in[13];
    const float* brel  = (const float*)d_in[14];
    const float* Wproj = (const float*)d_in[15];
    const float* bproj = (const float*)d_in[16];
    const float* W1    = (const float*)d_in[17];
    const float* bW1   = (const float*)d_in[18];
    const float* gng   = (const float*)d_in[19];
    const float* gnb   = (const float*)d_in[20];
    const float* Wdw   = (const float*)d_in[21];
    const float* W2    = (const float*)d_in[22];
    const float* bW2   = (const float*)d_in[23];
    float* out = (float*)d_out;

    float *qln, *kln, *vln, *Q, *K, *V, *att, *x1, *ln2, *h1, *cv;
    cudaGetSymbolAddress((void**)&qln, g_qln);
    cudaGetSymbolAddress((void**)&kln, g_kln);
    cudaGetSymbolAddress((void**)&vln, g_vln);
    cudaGetSymbolAddress((void**)&Q,   g_Q);
    cudaGetSymbolAddress((void**)&K,   g_K);
    cudaGetSymbolAddress((void**)&V,   g_V);
    cudaGetSymbolAddress((void**)&att, g_att);
    cudaGetSymbolAddress((void**)&x1,  g_x1);
    cudaGetSymbolAddress((void**)&ln2, g_ln2);
    cudaGetSymbolAddress((void**)&h1,  g_h1);
    cudaGetSymbolAddress((void**)&cv,  g_cv);

    int smem128 = (2*128*KP + 2*BN*KP) * sizeof(float);
    int smem64  = (2*64*KP  + 2*BN*KP) * sizeof(float);
    cudaFuncSetAttribute(mma_gemm_kernel<128>,
                         cudaFuncAttributeMaxDynamicSharedMemorySize, smem128);
    cudaFuncSetAttribute(mma_gemm_kernel<64>,
                         cudaFuncAttributeMaxDynamicSharedMemorySize, smem64);
    cudaFuncSetAttribute(mma_qkv_kernel,
                         cudaFuncAttributeMaxDynamicSharedMemorySize, smem128);

    // 1. LayerNorms (coalesced)
    ln3_kernel<<<TOK/32, 256>>>(img, imw, msk, ln1g, ln1b);

    // 2. QKV projections
    QKVArgs qa;
    qa.A[0] = qln; qa.A[1] = kln; qa.A[2] = vln;
    qa.W[0] = Wq;  qa.W[1] = Wk;  qa.W[2] = Wv;
    qa.bias[0] = bq; qa.bias[1] = bk; qa.bias[2] = bv;
    qa.C[0] = Q; qa.C[1] = K; qa.C[2] = V;
    mma_qkv_kernel<<<dim3(Cd/BN, TOK/128, 3), 256, smem128>>>(qa);

    // 3. tiled windowed attention (round-4 layout)
    int attn_smem = (32*KPAD + 32*WPAD + 16*SPAD + 16) * sizeof(float);
    cudaFuncSetAttribute(attn_tile_kernel,
                         cudaFuncAttributeMaxDynamicSharedMemorySize, attn_smem);
    attn_tile_kernel<<<dim3((Hh/QT)*(Wd/QT), NHd, Bz), 256, attn_smem>>>(Wrel, brel);

    // 4. output projection + fused residual -> x1  (BM=64, grid 200)
    mma_gemm_kernel<64><<<dim3(Cd/BN, TOK/64), 256, smem64>>>(att, Wproj, bproj, x1,
                                                              Cd, Cd, 1, img);

    // 5. MLP branch
    ln_tok_kernel<<<TOK, 256>>>(ln2g, ln2b);
    mma_gemm_kernel<128><<<dim3(HIDd/BN, TOK/128), 256, smem128>>>(ln2, W1, bW1, h1,
                                                                   HIDd, Cd, 0, nullptr);
    gn_stats_kernel<<<Bz*GNg, 256>>>();
    dwconv_fused_kernel<<<dim3(25, HIDd/64, Bz), 256>>>(gng, gnb, Wdw);

    // 6. W2 + fused final residual + transpose to BCHW  (BM=64, grid 200)
    mma_gemm_kernel<64><<<dim3(Cd/BN, TOK/64), 256, smem64>>>(cv, W2, bW2, out,
                                                              Cd, HIDd, 2, x1);
}